// round 14
// baseline (speedup 1.0000x reference)
#include <cuda_runtime.h>

#define N_NODES 50000
#define EDGE_F  13
#define HID     32
#define NB      8            // nodes per main block (deg<=32 -> <=256 edges)
#define CH      128          // edges per staging chunk
#define PAIRS   64           // CH/2
#define XS      9            // Xq row stride in ull2 (pad: write conflicts 4->2)
#define EFS     66           // EFp/Hp row stride in ull (16B-aligned, even)
#define EX      16           // node-0 slice blocks (first in grid)
#define NBLK    ((N_NODES + NB - 1) / NB)   // 6250
#define SCAN_B  512
#define SCAN_NB ((N_NODES + SCAN_B - 1) / SCAN_B)   // 98

typedef unsigned long long ull;

__device__ ulonglong2 W2Q[128][16];   // k-paired packed W2 (8 KB, L1-hot)
__device__ ull        b2P[8][16];
__device__ ull        Mg0x[EX][256];
__device__ float      Sg0x[EX][16];
__device__ int        StartsG[N_NODES];
__device__ int        PsumG[128];
__device__ int        OffG[128];
__device__ int        Ctr0;           // node-0 completion counter (self-resetting)
__device__ int        ScanCtr;        // scan completion counter (self-resetting)

// ---- packed fp32x2 helpers (sm_103a FFMA2, PTX-only) ----
__device__ __forceinline__ ull pk2(float a, float b) {
    ull r; asm("mov.b64 %0, {%1,%2};" : "=l"(r) : "f"(a), "f"(b)); return r;
}
__device__ __forceinline__ ull ffma2(ull a, ull b, ull c) {
    ull d; asm("fma.rn.f32x2 %0, %1, %2, %3;" : "=l"(d) : "l"(a), "l"(b), "l"(c)); return d;
}
__device__ __forceinline__ ull add2(ull a, ull b) {
    ull d; asm("add.rn.f32x2 %0, %1, %2;" : "=l"(d) : "l"(a), "l"(b)); return d;
}
__device__ __forceinline__ float2 unpk(ull a) {
    float2 f; asm("mov.b64 {%0,%1}, %2;" : "=f"(f.x), "=f"(f.y) : "l"(a)); return f;
}

// ---------------------------------------------------------------------------
// scan1 + pack + scan2 fused
// ---------------------------------------------------------------------------
__global__ void scan1_kernel(const float* __restrict__ degs,
                             const float* __restrict__ W2,
                             const float* __restrict__ b2)
{
    if (blockIdx.x == SCAN_NB) {
        int tid = threadIdx.x;
        for (int t = tid; t < 128 * 16; t += SCAN_B) {
            int k2 = t >> 4, o = t & 15;
            int k0 = 2 * k2, k1 = 2 * k2 + 1;
            int j0 = k0 >> 3, p0 = k0 & 7;
            int j1 = k1 >> 3, p1 = k1 & 7;
            ulonglong2 v;
            v.x = pk2(__ldg(W2 + j0 * 256 + 2 * p0 * 16 + o),
                      __ldg(W2 + j0 * 256 + (2 * p0 + 1) * 16 + o));
            v.y = pk2(__ldg(W2 + j1 * 256 + 2 * p1 * 16 + o),
                      __ldg(W2 + j1 * 256 + (2 * p1 + 1) * 16 + o));
            W2Q[k2][o] = v;
        }
        if (tid < 128) {
            int pp = tid >> 4, o = tid & 15;
            b2P[pp][o] = pk2(__ldg(b2 + 2 * pp * 16 + o),
                             __ldg(b2 + (2 * pp + 1) * 16 + o));
        }
        return;
    }
    __shared__ int s[SCAN_B];
    __shared__ int lastFlag;
    int b = blockIdx.x, t = threadIdx.x, n = b * SCAN_B + t;
    int d = (n < N_NODES) ? (int)degs[n] : 0;
    s[t] = d;
    for (int off = 1; off < SCAN_B; off <<= 1) {
        __syncthreads();
        int v = (t >= off) ? s[t - off] : 0;
        __syncthreads();
        s[t] += v;
    }
    if (n < N_NODES) StartsG[n] = s[t] - d;     // exclusive
    if (t == SCAN_B - 1) PsumG[b] = s[t];
    __threadfence();
    if (t == 0)
        lastFlag = (atomicAdd(&ScanCtr, 1) == SCAN_NB - 1) ? 1 : 0;
    __syncthreads();
    if (lastFlag) {
        __threadfence();
        if (t < 128) s[t] = (t < SCAN_NB) ? PsumG[t] : 0;
        __syncthreads();
        if (t == 0) {
            int acc = 0;
            for (int i = 0; i < SCAN_NB; i++) { int v = s[i]; s[i] = acc; acc += v; }
            ScanCtr = 0;
        }
        __syncthreads();
        if (t < SCAN_NB) OffG[t] = s[t];
    }
}

// ---------------------------------------------------------------------------
struct __align__(16) SmemT {
    ulonglong2 Xq[PAIRS][XS];     // 9.2 KB  x pairs, padded rows (144B)
    ull Mbuf[NB][260];            // 16.6 KB (16B-aligned rows)
    ull Hp[HID][EFS];             // 16.9 KB; GEMM partials + node0 scratch alias
    ull EFp[EDGE_F][EFS];         // 6.9 KB
    ull W1s[EDGE_F][HID];         // 3.3 KB packed {w,w}
    ull b1s[HID];
    ull Sb2[NB][8];
    int sb[NB + 4];
};                                // ~53.7 KB -> 4 blocks/SM

// h-compute: one 8-pair group per thread, bounded by QN
#define H_COMPUTE(QN)                                                      \
    {                                                                      \
        const int qb = tid >> 5, jj = tid & 31;                            \
        if (qb * 8 < (QN)) {                                               \
            ull hh0, hh1, hh2, hh3, hh4, hh5, hh6, hh7;                    \
            { ull bb = SM->b1s[jj];                                        \
              hh0 = bb; hh1 = bb; hh2 = bb; hh3 = bb;                      \
              hh4 = bb; hh5 = bb; hh6 = bb; hh7 = bb; }                    \
            _Pragma("unroll")                                              \
            for (int f = 0; f < EDGE_F; f++) {                             \
                ull w = SM->W1s[f][jj];                                    \
                const ull* efr = &SM->EFp[f][qb * 8];                      \
                ulonglong2 eA = *(const ulonglong2*)(efr);                 \
                ulonglong2 eB = *(const ulonglong2*)(efr + 2);             \
                hh0 = ffma2(eA.x, w, hh0); hh1 = ffma2(eA.y, w, hh1);      \
                hh2 = ffma2(eB.x, w, hh2); hh3 = ffma2(eB.y, w, hh3);      \
                ulonglong2 eC = *(const ulonglong2*)(efr + 4);             \
                ulonglong2 eD = *(const ulonglong2*)(efr + 6);             \
                hh4 = ffma2(eC.x, w, hh4); hh5 = ffma2(eC.y, w, hh5);      \
                hh6 = ffma2(eD.x, w, hh6); hh7 = ffma2(eD.y, w, hh7);      \
            }                                                              \
            ull* hdst = &SM->Hp[jj][qb * 8];                               \
            float2 fA, fB; ulonglong2 ov;                                  \
            fA = unpk(hh0); fB = unpk(hh1);                                \
            ov.x = pk2(fmaxf(fA.x, 0.f), fmaxf(fA.y, 0.f));                \
            ov.y = pk2(fmaxf(fB.x, 0.f), fmaxf(fB.y, 0.f));                \
            *(ulonglong2*)(hdst) = ov;                                     \
            fA = unpk(hh2); fB = unpk(hh3);                                \
            ov.x = pk2(fmaxf(fA.x, 0.f), fmaxf(fA.y, 0.f));                \
            ov.y = pk2(fmaxf(fB.x, 0.f), fmaxf(fB.y, 0.f));                \
            *(ulonglong2*)(hdst + 2) = ov;                                 \
            fA = unpk(hh4); fB = unpk(hh5);                                \
            ov.x = pk2(fmaxf(fA.x, 0.f), fmaxf(fA.y, 0.f));                \
            ov.y = pk2(fmaxf(fB.x, 0.f), fmaxf(fB.y, 0.f));                \
            *(ulonglong2*)(hdst + 4) = ov;                                 \
            fA = unpk(hh6); fB = unpk(hh7);                                \
            ov.x = pk2(fmaxf(fA.x, 0.f), fmaxf(fA.y, 0.f));                \
            ov.y = pk2(fmaxf(fB.x, 0.f), fmaxf(fB.y, 0.f));                \
            *(ulonglong2*)(hdst + 6) = ov;                                 \
        }                                                                  \
    }

// stage x row of edge e (thread t covers quarter r) into padded Xq
#define X_STORE(Q, R, HH, V)                                               \
    { float* c0 = (float*)&SM->Xq[Q][2 * (R)];                             \
      float* c1 = (float*)&SM->Xq[Q][2 * (R) + 1];                         \
      c0[HH]     = (V).x;  c0[2 + (HH)] = (V).y;                           \
      c1[HH]     = (V).z;  c1[2 + (HH)] = (V).w; }

__global__ void __launch_bounds__(256, 4)
fused_kernel(const float* __restrict__ x,
             const float* __restrict__ ef,
             const float* __restrict__ W1,
             const float* __restrict__ b1,
             const int*   __restrict__ idxn,
             const float* __restrict__ degs,
             float* __restrict__ out,
             int E)
{
    extern __shared__ char smem_raw[];
    SmemT* SM = (SmemT*)smem_raw;
    const int tid = threadIdx.x;
    const int bx  = blockIdx.x;
    const int j = tid >> 3, p = tid & 7;
    const int wS = tid >> 5, laneS = tid & 31;

    for (int t = tid; t < EDGE_F * HID; t += 256) {
        float w = __ldg(W1 + t);
        SM->W1s[t / HID][t % HID] = pk2(w, w);
    }
    if (tid < HID) { float bb = __ldg(b1 + tid); SM->b1s[tid] = pk2(bb, bb); }

    float* EFf = (float*)SM->EFp;       // row stride 2*EFS floats
    const ull* hrow = SM->Hp[j];
    const ulonglong2* xrow = &SM->Xq[0][p];    // advance by XS per q

    // EF staging index seeds (increment trick: +256 => e+=19, f+=9 w/ carry)
    const int e0 = tid / EDGE_F;
    const int f0 = tid - e0 * EDGE_F;

    if (bx >= EX) {
        // ================= main blocks: 8 nodes =================
        const int mb = bx - EX;
        const int t0 = (mb == 0) ? 1 : mb * NB;
        int t1 = mb * NB + NB; if (t1 > N_NODES) t1 = N_NODES;
        const int nn = t1 - t0;

        if (tid <= NB) {
            int target = t0 + tid; if (target > t1) target = t1;
            SM->sb[tid] = (target >= N_NODES) ? E
                          : (StartsG[target] + OffG[target >> 9]);
        }
        __syncthreads();

        const int es = SM->sb[0];
        const int ee = SM->sb[NB];
        ull a0 = 0ull, a1 = 0ull, aS = 0ull;

        for (int base = es; base < ee; base += CH) {
            const int c = min(CH, ee - base);
            const int cpad = (c + 1) & ~1;
            const int qn = cpad >> 1;

            if (c == CH) {
                // ---- fast path: full chunk, no guards ----
                {
                    int e = e0, f = f0;
                    const float* efg = ef + (size_t)base * EDGE_F;
                    #pragma unroll
                    for (int k = tid; k < CH * EDGE_F; k += 256) {
                        EFf[f * (2 * EFS) + e] = __ldg(efg + k);
                        e += 19; f += 9; if (f >= EDGE_F) { f -= EDGE_F; e++; }
                    }
                }
                #pragma unroll
                for (int t = tid; t < CH * 4; t += 256) {
                    int e = t >> 2, r = t & 3;
                    int src = __ldg(idxn + base + e);
                    float4 v = __ldg((const float4*)x + (size_t)src * 4 + r);
                    X_STORE(e >> 1, r, e & 1, v);
                }
            } else {
                // ---- slow path: partial chunk ----
                {
                    int e = e0, f = f0;
                    const float* efg = ef + (size_t)base * EDGE_F;
                    for (int k = tid; k < cpad * EDGE_F; k += 256) {
                        EFf[f * (2 * EFS) + e] = (e < c) ? __ldg(efg + k) : 0.f;
                        e += 19; f += 9; if (f >= EDGE_F) { f -= EDGE_F; e++; }
                    }
                }
                for (int t = tid; t < cpad * 4; t += 256) {
                    int e = t >> 2, r = t & 3;
                    float4 v = make_float4(0.f, 0.f, 0.f, 0.f);
                    if (e < c) {
                        int src = __ldg(idxn + base + e);
                        v = __ldg((const float4*)x + (size_t)src * 4 + r);
                    }
                    X_STORE(e >> 1, r, e & 1, v);
                }
            }
            __syncthreads();

            H_COMPUTE(qn);
            __syncthreads();

            const int cend = base + c;
            #pragma unroll 1
            for (int k = 0; k < NB; k++) {
                const int ak = SM->sb[k], bk = SM->sb[k + 1];
                int aL = ak - base; if (aL < 0) aL = 0;
                int bL = bk - base; if (bL > c) bL = c;
                if (bL > aL) {
                    const int qs = aL >> 1, qe = (bL - 1) >> 1;
                    const ull mlo = (aL & 1) ? 0xFFFFFFFF00000000ull : ~0ull;
                    const ull mhi = (bL & 1) ? 0x00000000FFFFFFFFull : ~0ull;
                    const ull* hp = &hrow[qs];
                    const ulonglong2* xp = xrow + (size_t)qs * XS;
                    if (qe == qs) {
                        ull h2 = *hp & (mlo & mhi);
                        ulonglong2 xv = *xp;
                        a0 = ffma2(h2, xv.x, a0); a1 = ffma2(h2, xv.y, a1);
                    } else {
                        {   // first (masked)
                            ull h2 = *hp & mlo;
                            ulonglong2 xv = *xp;
                            a0 = ffma2(h2, xv.x, a0); a1 = ffma2(h2, xv.y, a1);
                            hp++; xp += XS;
                        }
                        int q = qs + 1;
                        if ((q & 1) && q < qe) {       // align to even q
                            ull h2 = *hp;
                            ulonglong2 xv = *xp;
                            a0 = ffma2(h2, xv.x, a0); a1 = ffma2(h2, xv.y, a1);
                            hp++; xp += XS; q++;
                        }
                        #pragma unroll 4
                        for (; q + 1 < qe; q += 2) {   // two pairs: LDS.128 on h
                            ulonglong2 h4 = *(const ulonglong2*)hp;
                            ulonglong2 xv0 = xp[0];
                            ulonglong2 xv1 = xp[XS];
                            a0 = ffma2(h4.x, xv0.x, a0); a1 = ffma2(h4.x, xv0.y, a1);
                            a0 = ffma2(h4.y, xv1.x, a0); a1 = ffma2(h4.y, xv1.y, a1);
                            hp += 2; xp += 2 * XS;
                        }
                        if (q < qe) {
                            ull h2 = *hp;
                            ulonglong2 xv = *xp;
                            a0 = ffma2(h2, xv.x, a0); a1 = ffma2(h2, xv.y, a1);
                            hp++; xp += XS; q++;
                        }
                        {   // last (masked)
                            ull h2 = *hp & mhi;
                            ulonglong2 xv = *xp;
                            a0 = ffma2(h2, xv.x, a0); a1 = ffma2(h2, xv.y, a1);
                        }
                    }
                }
                if (bk > base && bk <= cend && bk > ak) {
                    float2 fa = unpk(a0), fb = unpk(a1);
                    SM->Mbuf[k][tid] = pk2(fa.x + fa.y, fb.x + fb.y);
                    a0 = 0ull; a1 = 0ull;
                }
            }

            // ---- S phase: warp wS owns node wS ----
            if (laneS < 16) {
                const int ak = SM->sb[wS], bk = SM->sb[wS + 1];
                int aL = ak - base; if (aL < 0) aL = 0;
                int bL = bk - base; if (bL > c) bL = c;
                if (bL > aL) {
                    const int qs = aL >> 1, qe = (bL - 1) >> 1;
                    const ull mlo = (aL & 1) ? 0xFFFFFFFF00000000ull : ~0ull;
                    const ull mhi = (bL & 1) ? 0x00000000FFFFFFFFull : ~0ull;
                    const ull* xrp = (const ull*)&SM->Xq[qs][laneS >> 1] + (laneS & 1);
                    ull x2 = *xrp & mlo;
                    if (qe == qs) x2 &= mhi;
                    aS = add2(aS, x2);
                    xrp += 2 * XS;
                    for (int q = qs + 1; q < qe; q++, xrp += 2 * XS)
                        aS = add2(aS, *xrp);
                    if (qe > qs) aS = add2(aS, *xrp & mhi);
                }
                if (bk > base && bk <= cend && bk > ak) {
                    float2 fs = unpk(aS);
                    ((float*)SM->Sb2)[wS * 16 + laneS] = fs.x + fs.y;
                    aS = 0ull;
                }
            }
            __syncthreads();
        }

        // ---- GEMM: 8-way k-split, each warp covers all 8 nodes ----
        {
            const int w = tid >> 5, lane = tid & 31;
            const int o = lane & 15, gh = lane >> 4;
            ull s0g = 0ull, s1g = 0ull, s2g = 0ull, s3g = 0ull;
            const ulonglong2* wp = &W2Q[w * 16][o];
            const ull* mb0 = &SM->Mbuf[gh * 4 + 0][2 * (w * 16)];
            const ull* mb1 = &SM->Mbuf[gh * 4 + 1][2 * (w * 16)];
            const ull* mb2 = &SM->Mbuf[gh * 4 + 2][2 * (w * 16)];
            const ull* mb3 = &SM->Mbuf[gh * 4 + 3][2 * (w * 16)];
            #pragma unroll 4
            for (int it = 0; it < 16; it++) {
                ulonglong2 w2 = __ldg(wp); wp += 16;
                ulonglong2 m0 = *(const ulonglong2*)mb0; mb0 += 2;
                ulonglong2 m1 = *(const ulonglong2*)mb1; mb1 += 2;
                ulonglong2 m2 = *(const ulonglong2*)mb2; mb2 += 2;
                ulonglong2 m3 = *(const ulonglong2*)mb3; mb3 += 2;
                s0g = ffma2(m0.x, w2.x, s0g); s0g = ffma2(m0.y, w2.y, s0g);
                s1g = ffma2(m1.x, w2.x, s1g); s1g = ffma2(m1.y, w2.y, s1g);
                s2g = ffma2(m2.x, w2.x, s2g); s2g = ffma2(m2.y, w2.y, s2g);
                s3g = ffma2(m3.x, w2.x, s3g); s3g = ffma2(m3.y, w2.y, s3g);
            }
            ull* Gred = &SM->Hp[0][0];
            Gred[w * 128 + (gh * 4 + 0) * 16 + o] = s0g;
            Gred[w * 128 + (gh * 4 + 1) * 16 + o] = s1g;
            Gred[w * 128 + (gh * 4 + 2) * 16 + o] = s2g;
            Gred[w * 128 + (gh * 4 + 3) * 16 + o] = s3g;
        }
        __syncthreads();
        if (tid < 128) {
            const int g = tid >> 4, o = tid & 15;
            const ull* Gred = &SM->Hp[0][0];
            ull s = Gred[g * 16 + o];
            #pragma unroll
            for (int w = 1; w < 8; w++) s = add2(s, Gred[w * 128 + g * 16 + o]);
            #pragma unroll
            for (int pp = 0; pp < 8; pp++)
                s = ffma2(SM->Sb2[g][pp], __ldg(&b2P[0][0] + pp * 16 + o), s);
            if (g < nn) {
                float2 f = unpk(s);
                float d = __ldg(degs + t0 + g);
                out[(t0 + g) * 16 + o] = (d > 0.f) ? (f.x + f.y) / d : 0.f;
            }
        }
    } else {
        // ================= node-0 slice blocks =================
        const int e0e = (int)__ldg(degs);
        ull a0 = 0ull, a1 = 0ull, aS = 0ull;
        __syncthreads();

        for (int base = bx * CH; base < e0e; base += EX * CH) {
            const int c = min(CH, e0e - base);
            const int cpad = (c + 1) & ~1;
            const int qn = cpad >> 1;

            if (c == CH) {
                {
                    int e = e0, f = f0;
                    const float* efg = ef + (size_t)base * EDGE_F;
                    #pragma unroll
                    for (int k = tid; k < CH * EDGE_F; k += 256) {
                        EFf[f * (2 * EFS) + e] = __ldg(efg + k);
                        e += 19; f += 9; if (f >= EDGE_F) { f -= EDGE_F; e++; }
                    }
                }
                #pragma unroll
                for (int t = tid; t < CH * 4; t += 256) {
                    int e = t >> 2, r = t & 3;
                    int src = __ldg(idxn + base + e);
                    float4 v = __ldg((const float4*)x + (size_t)src * 4 + r);
                    X_STORE(e >> 1, r, e & 1, v);
                }
            } else {
                {
                    int e = e0, f = f0;
                    const float* efg = ef + (size_t)base * EDGE_F;
                    for (int k = tid; k < cpad * EDGE_F; k += 256) {
                        EFf[f * (2 * EFS) + e] = (e < c) ? __ldg(efg + k) : 0.f;
                        e += 19; f += 9; if (f >= EDGE_F) { f -= EDGE_F; e++; }
                    }
                }
                for (int t = tid; t < cpad * 4; t += 256) {
                    int e = t >> 2, r = t & 3;
                    float4 v = make_float4(0.f, 0.f, 0.f, 0.f);
                    if (e < c) {
                        int src = __ldg(idxn + base + e);
                        v = __ldg((const float4*)x + (size_t)src * 4 + r);
                    }
                    X_STORE(e >> 1, r, e & 1, v);
                }
            }
            __syncthreads();

            H_COMPUTE(qn);
            __syncthreads();

            {
                const ull* hp = hrow;
                const ulonglong2* xp = xrow;
                int q = 0;
                #pragma unroll 4
                for (; q + 1 < qn; q += 2) {
                    ulonglong2 h4 = *(const ulonglong2*)hp;
                    ulonglong2 xv0 = xp[0];
                    ulonglong2 xv1 = xp[XS];
                    a0 = ffma2(h4.x, xv0.x, a0); a1 = ffma2(h4.x, xv0.y, a1);
                    a0 = ffma2(h4.y, xv1.x, a0); a1 = ffma2(h4.y, xv1.y, a1);
                    hp += 2; xp += 2 * XS;
                }
                if (q < qn) {
                    ull h2 = *hp;
                    ulonglong2 xv = *xp;
                    a0 = ffma2(h2, xv.x, a0); a1 = ffma2(h2, xv.y, a1);
                }
            }
            if (tid < 16) {
                const ull* xrp = (const ull*)&SM->Xq[0][tid >> 1] + (tid & 1);
                for (int q = 0; q < qn; q++, xrp += 2 * XS)
                    aS = add2(aS, *xrp);
            }
            __syncthreads();
        }
        {
            float2 fa = unpk(a0), fb = unpk(a1);
            Mg0x[bx][tid] = pk2(fa.x + fa.y, fb.x + fb.y);
            if (tid < 16) {
                float2 fs = unpk(aS);
                Sg0x[bx][tid] = fs.x + fs.y;
            }
        }

        // ---- last-arriving EX block reduces node 0 ----
        __threadfence();
        __syncthreads();
        if (tid == 0)
            SM->sb[0] = (atomicAdd(&Ctr0, 1) == EX - 1) ? 1 : 0;
        __syncthreads();
        if (SM->sb[0]) {
            __threadfence();
            float* wred = (float*)&SM->Mbuf[0][0];
            float* ssum = wred + 128;
            const int lane = tid & 31, w = tid >> 5;

            ull m = Mg0x[0][tid];
            #pragma unroll
            for (int e2 = 1; e2 < EX; e2++) m = add2(m, Mg0x[e2][tid]);
            if (tid < 16) {
                float s = 0.f;
                #pragma unroll
                for (int e2 = 0; e2 < EX; e2++) s += Sg0x[e2][tid];
                ssum[tid] = s;
            }
            float po[16];
            #pragma unroll
            for (int o = 0; o < 16; o++) {
                ull wk = ((const ull*)&W2Q[tid >> 1][o])[tid & 1];
                ull t2 = ffma2(m, wk, 0ull);
                float2 f = unpk(t2);
                po[o] = f.x + f.y;
            }
            #pragma unroll
            for (int o = 0; o < 16; o++)
                #pragma unroll
                for (int off = 16; off; off >>= 1)
                    po[o] += __shfl_down_sync(0xffffffffu, po[o], off);
            if (lane == 0)
                #pragma unroll
                for (int o = 0; o < 16; o++) wred[w * 16 + o] = po[o];
            __syncthreads();
            if (tid < 16) {
                float t = 0.f;
                #pragma unroll
                for (int w2 = 0; w2 < 8; w2++) t += wred[w2 * 16 + tid];
                float s2 = 0.f;
                #pragma unroll
                for (int pp = 0; pp < 8; pp++) {
                    ull q = ffma2(pk2(ssum[2 * pp], ssum[2 * pp + 1]),
                                  b2P[pp][tid], 0ull);
                    float2 f = unpk(q);
                    s2 += f.x + f.y;
                }
                float d = __ldg(degs);
                out[tid] = (d > 0.f) ? (t + s2) / d : 0.f;
            }
            if (tid == 0) Ctr0 = 0;
        }
    }
}

// ---------------------------------------------------------------------------
extern "C" void kernel_launch(void* const* d_in, const int* in_sizes, int n_in,
                              void* d_out, int out_size)
{
    const float* x    = (const float*)d_in[0];
    const float* ef   = (const float*)d_in[1];
    const float* W1   = (const float*)d_in[2];
    const float* b1   = (const float*)d_in[3];
    const float* W2   = (const float*)d_in[4];
    const float* b2   = (const float*)d_in[5];
    const int*   idxn = (const int*)d_in[6];
    const float* degs = (const float*)d_in[8];
    float* out = (float*)d_out;

    const int E = in_sizes[6];
    static int smem_set = 0;
    if (!smem_set) {
        cudaFuncSetAttribute(fused_kernel,
                             cudaFuncAttributeMaxDynamicSharedMemorySize,
                             (int)sizeof(SmemT));
        smem_set = 1;
    }

    scan1_kernel<<<SCAN_NB + 1, SCAN_B>>>(degs, W2, b2);
    fused_kernel<<<EX + NBLK, 256, sizeof(SmemT)>>>(x, ef, W1, b1, idxn, degs, out, E);
}

// round 15
// speedup vs baseline: 1.5823x; 1.5823x over previous
#include <cuda_runtime.h>

#define N_NODES 50000
#define EDGE_F  13
#define HID     32
#define NB      8            // nodes per main block (deg<=32 -> <=256 edges)
#define CH      128          // edges per staging chunk
#define PAIRS   64           // CH/2
#define XS      9            // Xq row stride in ull2 (pad: staging write conflicts 4->2)
#define EFS     66           // EFp/Hp row stride in ull (16B-aligned, even)
#define EX      16           // node-0 slice blocks (first in grid)
#define NBLK    ((N_NODES + NB - 1) / NB)   // 6250
#define SCAN_B  512
#define SCAN_NB ((N_NODES + SCAN_B - 1) / SCAN_B)   // 98

typedef unsigned long long ull;

__device__ ulonglong2 W2Q[128][16];   // k-paired packed W2 (8 KB, L1-hot)
__device__ ull        b2P[8][16];
__device__ ull        Mg0x[EX][256];
__device__ float      Sg0x[EX][16];
__device__ int        StartsG[N_NODES];
__device__ int        PsumG[128];
__device__ int        OffG[128];
__device__ int        Ctr0;           // node-0 completion counter (self-resetting)
__device__ int        ScanCtr;        // scan completion counter (self-resetting)

// ---- packed fp32x2 helpers (sm_103a FFMA2, PTX-only) ----
__device__ __forceinline__ ull pk2(float a, float b) {
    ull r; asm("mov.b64 %0, {%1,%2};" : "=l"(r) : "f"(a), "f"(b)); return r;
}
__device__ __forceinline__ ull ffma2(ull a, ull b, ull c) {
    ull d; asm("fma.rn.f32x2 %0, %1, %2, %3;" : "=l"(d) : "l"(a), "l"(b), "l"(c)); return d;
}
__device__ __forceinline__ ull add2(ull a, ull b) {
    ull d; asm("add.rn.f32x2 %0, %1, %2;" : "=l"(d) : "l"(a), "l"(b)); return d;
}
__device__ __forceinline__ float2 unpk(ull a) {
    float2 f; asm("mov.b64 {%0,%1}, %2;" : "=f"(f.x), "=f"(f.y) : "l"(a)); return f;
}

// ---------------------------------------------------------------------------
// scan1 + pack + scan2 fused
// ---------------------------------------------------------------------------
__global__ void scan1_kernel(const float* __restrict__ degs,
                             const float* __restrict__ W2,
                             const float* __restrict__ b2)
{
    if (blockIdx.x == SCAN_NB) {
        int tid = threadIdx.x;
        for (int t = tid; t < 128 * 16; t += SCAN_B) {
            int k2 = t >> 4, o = t & 15;
            int k0 = 2 * k2, k1 = 2 * k2 + 1;
            int j0 = k0 >> 3, p0 = k0 & 7;
            int j1 = k1 >> 3, p1 = k1 & 7;
            ulonglong2 v;
            v.x = pk2(__ldg(W2 + j0 * 256 + 2 * p0 * 16 + o),
                      __ldg(W2 + j0 * 256 + (2 * p0 + 1) * 16 + o));
            v.y = pk2(__ldg(W2 + j1 * 256 + 2 * p1 * 16 + o),
                      __ldg(W2 + j1 * 256 + (2 * p1 + 1) * 16 + o));
            W2Q[k2][o] = v;
        }
        if (tid < 128) {
            int pp = tid >> 4, o = tid & 15;
            b2P[pp][o] = pk2(__ldg(b2 + 2 * pp * 16 + o),
                             __ldg(b2 + (2 * pp + 1) * 16 + o));
        }
        return;
    }
    __shared__ int s[SCAN_B];
    __shared__ int lastFlag;
    int b = blockIdx.x, t = threadIdx.x, n = b * SCAN_B + t;
    int d = (n < N_NODES) ? (int)degs[n] : 0;
    s[t] = d;
    for (int off = 1; off < SCAN_B; off <<= 1) {
        __syncthreads();
        int v = (t >= off) ? s[t - off] : 0;
        __syncthreads();
        s[t] += v;
    }
    if (n < N_NODES) StartsG[n] = s[t] - d;     // exclusive
    if (t == SCAN_B - 1) PsumG[b] = s[t];
    __threadfence();
    if (t == 0)
        lastFlag = (atomicAdd(&ScanCtr, 1) == SCAN_NB - 1) ? 1 : 0;
    __syncthreads();
    if (lastFlag) {
        __threadfence();
        if (t < 128) s[t] = (t < SCAN_NB) ? PsumG[t] : 0;
        __syncthreads();
        if (t == 0) {
            int acc = 0;
            for (int i = 0; i < SCAN_NB; i++) { int v = s[i]; s[i] = acc; acc += v; }
            ScanCtr = 0;
        }
        __syncthreads();
        if (t < SCAN_NB) OffG[t] = s[t];
    }
}

// ---------------------------------------------------------------------------
struct __align__(16) SmemT {
    ulonglong2 Xq[PAIRS][XS];     // 9.2 KB  x pairs, padded rows (144B)
    ull Mbuf[NB][260];            // 16.6 KB (16B-aligned rows)
    ull Hp[HID][EFS];             // 16.9 KB; GEMM partials + node0 scratch alias
    ull EFp[EDGE_F][EFS];         // 6.9 KB
    ull W1s[EDGE_F][HID];         // 3.3 KB packed {w,w}
    ull b1s[HID];
    ull Sb2[NB][8];
    int sb[NB + 4];
};                                // ~53.7 KB -> 4 blocks/SM

// h-compute: one 8-pair group per thread, bounded by QN
#define H_COMPUTE(QN)                                                      \
    {                                                                      \
        const int qb = tid >> 5, jj = tid & 31;                            \
        if (qb * 8 < (QN)) {                                               \
            ull hh0, hh1, hh2, hh3, hh4, hh5, hh6, hh7;                    \
            { ull bb = SM->b1s[jj];                                        \
              hh0 = bb; hh1 = bb; hh2 = bb; hh3 = bb;                      \
              hh4 = bb; hh5 = bb; hh6 = bb; hh7 = bb; }                    \
            _Pragma("unroll")                                              \
            for (int f = 0; f < EDGE_F; f++) {                             \
                ull w = SM->W1s[f][jj];                                    \
                const ull* efr = &SM->EFp[f][qb * 8];                      \
                ulonglong2 eA = *(const ulonglong2*)(efr);                 \
                ulonglong2 eB = *(const ulonglong2*)(efr + 2);             \
                hh0 = ffma2(eA.x, w, hh0); hh1 = ffma2(eA.y, w, hh1);      \
                hh2 = ffma2(eB.x, w, hh2); hh3 = ffma2(eB.y, w, hh3);      \
                ulonglong2 eC = *(const ulonglong2*)(efr + 4);             \
                ulonglong2 eD = *(const ulonglong2*)(efr + 6);             \
                hh4 = ffma2(eC.x, w, hh4); hh5 = ffma2(eC.y, w, hh5);      \
                hh6 = ffma2(eD.x, w, hh6); hh7 = ffma2(eD.y, w, hh7);      \
            }                                                              \
            ull* hdst = &SM->Hp[jj][qb * 8];                               \
            float2 fA, fB; ulonglong2 ov;                                  \
            fA = unpk(hh0); fB = unpk(hh1);                                \
            ov.x = pk2(fmaxf(fA.x, 0.f), fmaxf(fA.y, 0.f));                \
            ov.y = pk2(fmaxf(fB.x, 0.f), fmaxf(fB.y, 0.f));                \
            *(ulonglong2*)(hdst) = ov;                                     \
            fA = unpk(hh2); fB = unpk(hh3);                                \
            ov.x = pk2(fmaxf(fA.x, 0.f), fmaxf(fA.y, 0.f));                \
            ov.y = pk2(fmaxf(fB.x, 0.f), fmaxf(fB.y, 0.f));                \
            *(ulonglong2*)(hdst + 2) = ov;                                 \
            fA = unpk(hh4); fB = unpk(hh5);                                \
            ov.x = pk2(fmaxf(fA.x, 0.f), fmaxf(fA.y, 0.f));                \
            ov.y = pk2(fmaxf(fB.x, 0.f), fmaxf(fB.y, 0.f));                \
            *(ulonglong2*)(hdst + 4) = ov;                                 \
            fA = unpk(hh6); fB = unpk(hh7);                                \
            ov.x = pk2(fmaxf(fA.x, 0.f), fmaxf(fA.y, 0.f));                \
            ov.y = pk2(fmaxf(fB.x, 0.f), fmaxf(fB.y, 0.f));                \
            *(ulonglong2*)(hdst + 6) = ov;                                 \
        }                                                                  \
    }

__global__ void __launch_bounds__(256, 4)
fused_kernel(const float* __restrict__ x,
             const float* __restrict__ ef,
             const float* __restrict__ W1,
             const float* __restrict__ b1,
             const int*   __restrict__ idxn,
             const float* __restrict__ degs,
             float* __restrict__ out,
             int E)
{
    extern __shared__ char smem_raw[];
    SmemT* SM = (SmemT*)smem_raw;
    const int tid = threadIdx.x;
    const int bx  = blockIdx.x;
    const int j = tid >> 3, p = tid & 7;
    const int wS = tid >> 5, laneS = tid & 31;   // S-phase: warp wS owns node wS

    for (int t = tid; t < EDGE_F * HID; t += 256) {
        float w = __ldg(W1 + t);
        SM->W1s[t / HID][t % HID] = pk2(w, w);
    }
    if (tid < HID) { float bb = __ldg(b1 + tid); SM->b1s[tid] = pk2(bb, bb); }

    float* EFf = (float*)SM->EFp;       // row stride 2*EFS floats
    const ull* hrow = SM->Hp[j];
    const ulonglong2* xrow = &SM->Xq[0][p];    // advance by XS per q

    if (bx >= EX) {
        // ================= main blocks: 8 nodes =================
        const int mb = bx - EX;
        const int t0 = (mb == 0) ? 1 : mb * NB;     // node 0 excluded
        int t1 = mb * NB + NB; if (t1 > N_NODES) t1 = N_NODES;
        const int nn = t1 - t0;

        if (tid <= NB) {
            int target = t0 + tid; if (target > t1) target = t1;
            SM->sb[tid] = (target >= N_NODES) ? E
                          : (StartsG[target] + OffG[target >> 9]);
        }
        __syncthreads();

        const int es = SM->sb[0];
        const int ee = SM->sb[NB];
        ull a0 = 0ull, a1 = 0ull, aS = 0ull;

        for (int base = es; base < ee; base += CH) {
            const int c = min(CH, ee - base);
            const int cpad = (c + 1) & ~1;
            const int qn = cpad >> 1;

            // ---- stage ef (zero-padded to cpad) ----
            for (int k = tid; k < cpad * EDGE_F; k += 256) {
                int e = k / EDGE_F, f = k - e * EDGE_F;
                EFf[f * (2 * EFS) + e] =
                    (e < c) ? __ldg(ef + (size_t)base * EDGE_F + k) : 0.f;
            }
            // ---- stage x gather ----
            for (int t = tid; t < cpad * 4; t += 256) {
                int e = t >> 2, r = t & 3;
                float4 v = make_float4(0.f, 0.f, 0.f, 0.f);
                if (e < c) {
                    int src = __ldg(idxn + base + e);
                    v = __ldg((const float4*)x + (size_t)src * 4 + r);
                }
                int q = e >> 1, hh = e & 1;
                float* c0 = (float*)&SM->Xq[q][2 * r];
                float* c1 = (float*)&SM->Xq[q][2 * r + 1];
                c0[hh]     = v.x;
                c0[2 + hh] = v.y;
                c1[hh]     = v.z;
                c1[2 + hh] = v.w;
            }
            __syncthreads();

            // ---- h: 8-pair group per thread, bounded by qn ----
            H_COMPUTE(qn);
            __syncthreads();

            const int cend = base + c;
            // ---- per-node masked rank-1 accumulation ----
            #pragma unroll 1
            for (int k = 0; k < NB; k++) {
                const int ak = SM->sb[k], bk = SM->sb[k + 1];
                int aL = ak - base; if (aL < 0) aL = 0;
                int bL = bk - base; if (bL > c) bL = c;
                if (bL > aL) {
                    const int qs = aL >> 1, qe = (bL - 1) >> 1;
                    const ull mlo = (aL & 1) ? 0xFFFFFFFF00000000ull : ~0ull;
                    const ull mhi = (bL & 1) ? 0x00000000FFFFFFFFull : ~0ull;
                    const ull* hp = &hrow[qs];
                    const ulonglong2* xp = xrow + (size_t)qs * XS;
                    if (qe == qs) {
                        ull h2 = *hp & (mlo & mhi);
                        ulonglong2 xv = *xp;
                        a0 = ffma2(h2, xv.x, a0); a1 = ffma2(h2, xv.y, a1);
                    } else {
                        {   // first (masked)
                            ull h2 = *hp & mlo;
                            ulonglong2 xv = *xp;
                            a0 = ffma2(h2, xv.x, a0); a1 = ffma2(h2, xv.y, a1);
                            hp++; xp += XS;
                        }
                        int q = qs + 1;
                        if ((q & 1) && q < qe) {       // align to even q
                            ull h2 = *hp;
                            ulonglong2 xv = *xp;
                            a0 = ffma2(h2, xv.x, a0); a1 = ffma2(h2, xv.y, a1);
                            hp++; xp += XS; q++;
                        }
                        #pragma unroll 2
                        for (; q + 1 < qe; q += 2) {   // two pairs: LDS.128 on h
                            ulonglong2 h4 = *(const ulonglong2*)hp;
                            ulonglong2 xv0 = xp[0];
                            ulonglong2 xv1 = xp[XS];
                            a0 = ffma2(h4.x, xv0.x, a0); a1 = ffma2(h4.x, xv0.y, a1);
                            a0 = ffma2(h4.y, xv1.x, a0); a1 = ffma2(h4.y, xv1.y, a1);
                            hp += 2; xp += 2 * XS;
                        }
                        if (q < qe) {
                            ull h2 = *hp;
                            ulonglong2 xv = *xp;
                            a0 = ffma2(h2, xv.x, a0); a1 = ffma2(h2, xv.y, a1);
                            hp++; xp += XS; q++;
                        }
                        {   // last (masked)
                            ull h2 = *hp & mhi;
                            ulonglong2 xv = *xp;
                            a0 = ffma2(h2, xv.x, a0); a1 = ffma2(h2, xv.y, a1);
                        }
                    }
                }
                if (bk > base && bk <= cend && bk > ak) {   // segment ends here
                    float2 fa = unpk(a0), fb = unpk(a1);
                    SM->Mbuf[k][tid] = pk2(fa.x + fa.y, fb.x + fb.y);
                    a0 = 0ull; a1 = 0ull;
                }
            }

            // ---- S phase: warp wS owns node wS (lanes 0-15, i = laneS) ----
            if (laneS < 16) {
                const int ak = SM->sb[wS], bk = SM->sb[wS + 1];
                int aL = ak - base; if (aL < 0) aL = 0;
                int bL = bk - base; if (bL > c) bL = c;
                if (bL > aL) {
                    const int qs = aL >> 1, qe = (bL - 1) >> 1;
                    const ull mlo = (aL & 1) ? 0xFFFFFFFF00000000ull : ~0ull;
                    const ull mhi = (bL & 1) ? 0x00000000FFFFFFFFull : ~0ull;
                    const ull* xrp = (const ull*)&SM->Xq[qs][laneS >> 1] + (laneS & 1);
                    ull x2 = *xrp & mlo;
                    if (qe == qs) x2 &= mhi;
                    aS = add2(aS, x2);
                    xrp += 2 * XS;
                    for (int q = qs + 1; q < qe; q++, xrp += 2 * XS)
                        aS = add2(aS, *xrp);
                    if (qe > qs) aS = add2(aS, *xrp & mhi);
                }
                if (bk > base && bk <= cend && bk > ak) {
                    float2 fs = unpk(aS);
                    ((float*)SM->Sb2)[wS * 16 + laneS] = fs.x + fs.y;
                    aS = 0ull;
                }
            }
            __syncthreads();
        }

        // ---- GEMM: 8-way k-split, each warp covers all 8 nodes ----
        {
            const int w = tid >> 5, lane = tid & 31;
            const int o = lane & 15, gh = lane >> 4;     // gh: node half
            ull s0g = 0ull, s1g = 0ull, s2g = 0ull, s3g = 0ull;
            const ulonglong2* wp = &W2Q[w * 16][o];
            const ull* mb0 = &SM->Mbuf[gh * 4 + 0][2 * (w * 16)];
            const ull* mb1 = &SM->Mbuf[gh * 4 + 1][2 * (w * 16)];
            const ull* mb2 = &SM->Mbuf[gh * 4 + 2][2 * (w * 16)];
            const ull* mb3 = &SM->Mbuf[gh * 4 + 3][2 * (w * 16)];
            #pragma unroll 4
            for (int it = 0; it < 16; it++) {
                ulonglong2 w2 = __ldg(wp); wp += 16;
                ulonglong2 m0 = *(const ulonglong2*)mb0; mb0 += 2;
                ulonglong2 m1 = *(const ulonglong2*)mb1; mb1 += 2;
                ulonglong2 m2 = *(const ulonglong2*)mb2; mb2 += 2;
                ulonglong2 m3 = *(const ulonglong2*)mb3; mb3 += 2;
                s0g = ffma2(m0.x, w2.x, s0g); s0g = ffma2(m0.y, w2.y, s0g);
                s1g = ffma2(m1.x, w2.x, s1g); s1g = ffma2(m1.y, w2.y, s1g);
                s2g = ffma2(m2.x, w2.x, s2g); s2g = ffma2(m2.y, w2.y, s2g);
                s3g = ffma2(m3.x, w2.x, s3g); s3g = ffma2(m3.y, w2.y, s3g);
            }
            ull* Gred = &SM->Hp[0][0];       // Hp dead after last chunk
            Gred[w * 128 + (gh * 4 + 0) * 16 + o] = s0g;
            Gred[w * 128 + (gh * 4 + 1) * 16 + o] = s1g;
            Gred[w * 128 + (gh * 4 + 2) * 16 + o] = s2g;
            Gred[w * 128 + (gh * 4 + 3) * 16 + o] = s3g;
        }
        __syncthreads();
        if (tid < 128) {
            const int g = tid >> 4, o = tid & 15;
            const ull* Gred = &SM->Hp[0][0];
            ull s = Gred[g * 16 + o];
            #pragma unroll
            for (int w = 1; w < 8; w++) s = add2(s, Gred[w * 128 + g * 16 + o]);
            #pragma unroll
            for (int pp = 0; pp < 8; pp++)
                s = ffma2(SM->Sb2[g][pp], __ldg(&b2P[0][0] + pp * 16 + o), s);
            if (g < nn) {
                float2 f = unpk(s);
                float d = __ldg(degs + t0 + g);
                out[(t0 + g) * 16 + o] = (d > 0.f) ? (f.x + f.y) / d : 0.f;
            }
        }
    } else {
        // ================= node-0 slice blocks =================
        const int e0e = (int)__ldg(degs);   // node 0 owns edges [0, degs[0])
        ull a0 = 0ull, a1 = 0ull, aS = 0ull;
        __syncthreads();

        for (int base = bx * CH; base < e0e; base += EX * CH) {
            const int c = min(CH, e0e - base);
            const int cpad = (c + 1) & ~1;
            const int qn = cpad >> 1;

            for (int k = tid; k < cpad * EDGE_F; k += 256) {
                int e = k / EDGE_F, f = k - e * EDGE_F;
                EFf[f * (2 * EFS) + e] =
                    (e < c) ? __ldg(ef + (size_t)base * EDGE_F + k) : 0.f;
            }
            for (int t = tid; t < cpad * 4; t += 256) {
                int e = t >> 2, r = t & 3;
                float4 v = make_float4(0.f, 0.f, 0.f, 0.f);
                if (e < c) {
                    int src = __ldg(idxn + base + e);
                    v = __ldg((const float4*)x + (size_t)src * 4 + r);
                }
                int q = e >> 1, hh = e & 1;
                float* c0 = (float*)&SM->Xq[q][2 * r];
                float* c1 = (float*)&SM->Xq[q][2 * r + 1];
                c0[hh]     = v.x;
                c0[2 + hh] = v.y;
                c1[hh]     = v.z;
                c1[2 + hh] = v.w;
            }
            __syncthreads();

            H_COMPUTE(qn);
            __syncthreads();

            {
                const ull* hp = hrow;
                const ulonglong2* xp = xrow;
                int q = 0;
                #pragma unroll 2
                for (; q + 1 < qn; q += 2) {
                    ulonglong2 h4 = *(const ulonglong2*)hp;
                    ulonglong2 xv0 = xp[0];
                    ulonglong2 xv1 = xp[XS];
                    a0 = ffma2(h4.x, xv0.x, a0); a1 = ffma2(h4.x, xv0.y, a1);
                    a0 = ffma2(h4.y, xv1.x, a0); a1 = ffma2(h4.y, xv1.y, a1);
                    hp += 2; xp += 2 * XS;
                }
                if (q < qn) {
                    ull h2 = *hp;
                    ulonglong2 xv = *xp;
                    a0 = ffma2(h2, xv.x, a0); a1 = ffma2(h2, xv.y, a1);
                }
            }
            if (tid < 16) {
                const ull* xrp = (const ull*)&SM->Xq[0][tid >> 1] + (tid & 1);
                for (int q = 0; q < qn; q++, xrp += 2 * XS)
                    aS = add2(aS, *xrp);
            }
            __syncthreads();
        }
        {
            float2 fa = unpk(a0), fb = unpk(a1);
            Mg0x[bx][tid] = pk2(fa.x + fa.y, fb.x + fb.y);
            if (tid < 16) {
                float2 fs = unpk(aS);
                Sg0x[bx][tid] = fs.x + fs.y;
            }
        }

        // ---- last-arriving EX block reduces node 0 ----
        __threadfence();
        __syncthreads();
        if (tid == 0)
            SM->sb[0] = (atomicAdd(&Ctr0, 1) == EX - 1) ? 1 : 0;
        __syncthreads();
        if (SM->sb[0]) {
            __threadfence();
            float* wred = (float*)&SM->Mbuf[0][0];
            float* ssum = wred + 128;
            const int lane = tid & 31, w = tid >> 5;

            ull m = Mg0x[0][tid];
            #pragma unroll
            for (int e2 = 1; e2 < EX; e2++) m = add2(m, Mg0x[e2][tid]);
            if (tid < 16) {
                float s = 0.f;
                #pragma unroll
                for (int e2 = 0; e2 < EX; e2++) s += Sg0x[e2][tid];
                ssum[tid] = s;
            }
            float po[16];
            #pragma unroll
            for (int o = 0; o < 16; o++) {
                ull wk = ((const ull*)&W2Q[tid >> 1][o])[tid & 1];
                ull t2 = ffma2(m, wk, 0ull);
                float2 f = unpk(t2);
                po[o] = f.x + f.y;
            }
            #pragma unroll
            for (int o = 0; o < 16; o++)
                #pragma unroll
                for (int off = 16; off; off >>= 1)
                    po[o] += __shfl_down_sync(0xffffffffu, po[o], off);
            if (lane == 0)
                #pragma unroll
                for (int o = 0; o < 16; o++) wred[w * 16 + o] = po[o];
            __syncthreads();
            if (tid < 16) {
                float t = 0.f;
                #pragma unroll
                for (int w2 = 0; w2 < 8; w2++) t += wred[w2 * 16 + tid];
                float s2 = 0.f;
                #pragma unroll
                for (int pp = 0; pp < 8; pp++) {
                    ull q = ffma2(pk2(ssum[2 * pp], ssum[2 * pp + 1]),
                                  b2P[pp][tid], 0ull);
                    float2 f = unpk(q);
                    s2 += f.x + f.y;
                }
                float d = __ldg(degs);
                out[tid] = (d > 0.f) ? (t + s2) / d : 0.f;
            }
            if (tid == 0) Ctr0 = 0;
        }
    }
}

// ---------------------------------------------------------------------------
extern "C" void kernel_launch(void* const* d_in, const int* in_sizes, int n_in,
                              void* d_out, int out_size)
{
    const float* x    = (const float*)d_in[0];
    const float* ef   = (const float*)d_in[1];
    const float* W1   = (const float*)d_in[2];
    const float* b1   = (const float*)d_in[3];
    const float* W2   = (const float*)d_in[4];
    const float* b2   = (const float*)d_in[5];
    const int*   idxn = (const int*)d_in[6];
    const float* degs = (const float*)d_in[8];
    float* out = (float*)d_out;

    const int E = in_sizes[6];
    static int smem_set = 0;
    if (!smem_set) {
        cudaFuncSetAttribute(fused_kernel,
                             cudaFuncAttributeMaxDynamicSharedMemorySize,
                             (int)sizeof(SmemT));
        smem_set = 1;
    }

    scan1_kernel<<<SCAN_NB + 1, SCAN_B>>>(degs, W2, b2);
    fused_kernel<<<EX + NBLK, 256, sizeof(SmemT)>>>(x, ef, W1, b1, idxn, degs, out, E);
}

// round 17
// speedup vs baseline: 1.5985x; 1.0103x over previous
#include <cuda_runtime.h>

#define N_NODES 50000
#define EDGE_F  13
#define HID     32
#define NB      8            // nodes per main block (deg<=32 -> <=256 edges)
#define CH      128          // edges per staging chunk
#define PAIRS   64           // CH/2
#define XS      9            // Xq row stride in ull2 (pad: staging write conflicts 4->2)
#define EFS     66           // EFp/Hp row stride in ull (16B-aligned, even)
#define EX      16           // node-0 slice blocks (first in grid)
#define NBLK    ((N_NODES + NB - 1) / NB)   // 6250
#define SCAN_B  512
#define SCAN_NB ((N_NODES + SCAN_B - 1) / SCAN_B)   // 98

typedef unsigned long long ull;

__device__ ulonglong2 W2Q[128][16];   // k-paired packed W2 (8 KB, L1-hot)
__device__ ull        b2P[8][16];
__device__ ull        Mg0x[EX][256];
__device__ float      Sg0x[EX][16];
__device__ int        StartsG[N_NODES];
__device__ int        PsumG[128];
__device__ int        OffG[128];
__device__ int        Ctr0;           // node-0 completion counter (self-resetting)
__device__ int        ScanCtr;        // scan completion counter (self-resetting)

// ---- packed fp32x2 helpers (sm_103a FFMA2, PTX-only) ----
__device__ __forceinline__ ull pk2(float a, float b) {
    ull r; asm("mov.b64 %0, {%1,%2};" : "=l"(r) : "f"(a), "f"(b)); return r;
}
__device__ __forceinline__ ull ffma2(ull a, ull b, ull c) {
    ull d; asm("fma.rn.f32x2 %0, %1, %2, %3;" : "=l"(d) : "l"(a), "l"(b), "l"(c)); return d;
}
__device__ __forceinline__ ull add2(ull a, ull b) {
    ull d; asm("add.rn.f32x2 %0, %1, %2;" : "=l"(d) : "l"(a), "l"(b)); return d;
}
__device__ __forceinline__ float2 unpk(ull a) {
    float2 f; asm("mov.b64 {%0,%1}, %2;" : "=f"(f.x), "=f"(f.y) : "l"(a)); return f;
}

// ---------------------------------------------------------------------------
// scan1 + pack + scan2 fused
// ---------------------------------------------------------------------------
__global__ void scan1_kernel(const float* __restrict__ degs,
                             const float* __restrict__ W2,
                             const float* __restrict__ b2)
{
    if (blockIdx.x == SCAN_NB) {
        int tid = threadIdx.x;
        for (int t = tid; t < 128 * 16; t += SCAN_B) {
            int k2 = t >> 4, o = t & 15;
            int k0 = 2 * k2, k1 = 2 * k2 + 1;
            int j0 = k0 >> 3, p0 = k0 & 7;
            int j1 = k1 >> 3, p1 = k1 & 7;
            ulonglong2 v;
            v.x = pk2(__ldg(W2 + j0 * 256 + 2 * p0 * 16 + o),
                      __ldg(W2 + j0 * 256 + (2 * p0 + 1) * 16 + o));
            v.y = pk2(__ldg(W2 + j1 * 256 + 2 * p1 * 16 + o),
                      __ldg(W2 + j1 * 256 + (2 * p1 + 1) * 16 + o));
            W2Q[k2][o] = v;
        }
        if (tid < 128) {
            int pp = tid >> 4, o = tid & 15;
            b2P[pp][o] = pk2(__ldg(b2 + 2 * pp * 16 + o),
                             __ldg(b2 + (2 * pp + 1) * 16 + o));
        }
        return;
    }
    __shared__ int s[SCAN_B];
    __shared__ int lastFlag;
    int b = blockIdx.x, t = threadIdx.x, n = b * SCAN_B + t;
    int d = (n < N_NODES) ? (int)degs[n] : 0;
    s[t] = d;
    for (int off = 1; off < SCAN_B; off <<= 1) {
        __syncthreads();
        int v = (t >= off) ? s[t - off] : 0;
        __syncthreads();
        s[t] += v;
    }
    if (n < N_NODES) StartsG[n] = s[t] - d;     // exclusive
    if (t == SCAN_B - 1) PsumG[b] = s[t];
    __threadfence();
    if (t == 0)
        lastFlag = (atomicAdd(&ScanCtr, 1) == SCAN_NB - 1) ? 1 : 0;
    __syncthreads();
    if (lastFlag) {
        __threadfence();
        if (t < 128) s[t] = (t < SCAN_NB) ? PsumG[t] : 0;
        __syncthreads();
        if (t == 0) {
            int acc = 0;
            for (int i = 0; i < SCAN_NB; i++) { int v = s[i]; s[i] = acc; acc += v; }
            ScanCtr = 0;
        }
        __syncthreads();
        if (t < SCAN_NB) OffG[t] = s[t];
    }
}

// ---------------------------------------------------------------------------
struct __align__(16) SmemT {
    ulonglong2 Xq[PAIRS][XS];     // 9.2 KB  x pairs, padded rows (144B)
    ull Mbuf[NB][260];            // 16.6 KB (16B-aligned rows)
    ull Hp[HID][EFS];             // 16.9 KB; GEMM partials + node0 scratch alias
    ull EFp[EDGE_F][EFS];         // 6.9 KB
    ull W1s[EDGE_F][HID];         // 3.3 KB packed {w,w}
    ull b1s[HID];
    ull Sb2[NB][8];
    int sb[NB + 4];
    int segd[NB];                 // per-chunk: aL | bL<<9 | flush<<31 (aL,bL in [0,c])
};                                // ~53.8 KB -> 4 blocks/SM

// h-compute: one 8-pair group per thread, bounded by QN
#define H_COMPUTE(QN)                                                      \
    {                                                                      \
        const int qb = tid >> 5, jj = tid & 31;                            \
        if (qb * 8 < (QN)) {                                               \
            ull hh0, hh1, hh2, hh3, hh4, hh5, hh6, hh7;                    \
            { ull bb = SM->b1s[jj];                                        \
              hh0 = bb; hh1 = bb; hh2 = bb; hh3 = bb;                      \
              hh4 = bb; hh5 = bb; hh6 = bb; hh7 = bb; }                    \
            _Pragma("unroll")                                              \
            for (int f = 0; f < EDGE_F; f++) {                             \
                ull w = SM->W1s[f][jj];                                    \
                const ull* efr = &SM->EFp[f][qb * 8];                      \
                ulonglong2 eA = *(const ulonglong2*)(efr);                 \
                ulonglong2 eB = *(const ulonglong2*)(efr + 2);             \
                hh0 = ffma2(eA.x, w, hh0); hh1 = ffma2(eA.y, w, hh1);      \
                hh2 = ffma2(eB.x, w, hh2); hh3 = ffma2(eB.y, w, hh3);      \
                ulonglong2 eC = *(const ulonglong2*)(efr + 4);             \
                ulonglong2 eD = *(const ulonglong2*)(efr + 6);             \
                hh4 = ffma2(eC.x, w, hh4); hh5 = ffma2(eC.y, w, hh5);      \
                hh6 = ffma2(eD.x, w, hh6); hh7 = ffma2(eD.y, w, hh7);      \
            }                                                              \
            ull* hdst = &SM->Hp[jj][qb * 8];                               \
            float2 fA, fB; ulonglong2 ov;                                  \
            fA = unpk(hh0); fB = unpk(hh1);                                \
            ov.x = pk2(fmaxf(fA.x, 0.f), fmaxf(fA.y, 0.f));                \
            ov.y = pk2(fmaxf(fB.x, 0.f), fmaxf(fB.y, 0.f));                \
            *(ulonglong2*)(hdst) = ov;                                     \
            fA = unpk(hh2); fB = unpk(hh3);                                \
            ov.x = pk2(fmaxf(fA.x, 0.f), fmaxf(fA.y, 0.f));                \
            ov.y = pk2(fmaxf(fB.x, 0.f), fmaxf(fB.y, 0.f));                \
            *(ulonglong2*)(hdst + 2) = ov;                                 \
            fA = unpk(hh4); fB = unpk(hh5);                                \
            ov.x = pk2(fmaxf(fA.x, 0.f), fmaxf(fA.y, 0.f));                \
            ov.y = pk2(fmaxf(fB.x, 0.f), fmaxf(fB.y, 0.f));                \
            *(ulonglong2*)(hdst + 4) = ov;                                 \
            fA = unpk(hh6); fB = unpk(hh7);                                \
            ov.x = pk2(fmaxf(fA.x, 0.f), fmaxf(fA.y, 0.f));                \
            ov.y = pk2(fmaxf(fB.x, 0.f), fmaxf(fB.y, 0.f));                \
            *(ulonglong2*)(hdst + 6) = ov;                                 \
        }                                                                  \
    }

__global__ void __launch_bounds__(256, 4)
fused_kernel(const float* __restrict__ x,
             const float* __restrict__ ef,
             const float* __restrict__ W1,
             const float* __restrict__ b1,
             const int*   __restrict__ idxn,
             const float* __restrict__ degs,
             float* __restrict__ out,
             int E)
{
    extern __shared__ char smem_raw[];
    SmemT* SM = (SmemT*)smem_raw;
    const int tid = threadIdx.x;
    const int bx  = blockIdx.x;
    const int j = tid >> 3, p = tid & 7;
    const int wS = tid >> 5, laneS = tid & 31;   // S-phase: warp wS owns node wS

    for (int t = tid; t < EDGE_F * HID; t += 256) {
        float w = __ldg(W1 + t);
        SM->W1s[t / HID][t % HID] = pk2(w, w);
    }
    if (tid < HID) { float bb = __ldg(b1 + tid); SM->b1s[tid] = pk2(bb, bb); }

    float* EFf = (float*)SM->EFp;       // row stride 2*EFS floats
    const ull* hrow = SM->Hp[j];
    const ulonglong2* xrow = &SM->Xq[0][p];    // advance by XS per q

    if (bx >= EX) {
        // ================= main blocks: 8 nodes =================
        const int mb = bx - EX;
        const int t0 = (mb == 0) ? 1 : mb * NB;     // node 0 excluded
        int t1 = mb * NB + NB; if (t1 > N_NODES) t1 = N_NODES;
        const int nn = t1 - t0;

        if (tid <= NB) {
            int target = t0 + tid; if (target > t1) target = t1;
            SM->sb[tid] = (target >= N_NODES) ? E
                          : (StartsG[target] + OffG[target >> 9]);
        }
        __syncthreads();

        const int es = SM->sb[0];
        const int ee = SM->sb[NB];
        ull a0 = 0ull, a1 = 0ull, aS = 0ull;

        for (int base = es; base < ee; base += CH) {
            const int c = min(CH, ee - base);
            const int cpad = (c + 1) & ~1;
            const int qn = cpad >> 1;

            // ---- stage ef (zero-padded to cpad) ----
            for (int k = tid; k < cpad * EDGE_F; k += 256) {
                int e = k / EDGE_F, f = k - e * EDGE_F;
                EFf[f * (2 * EFS) + e] =
                    (e < c) ? __ldg(ef + (size_t)base * EDGE_F + k) : 0.f;
            }
            // ---- stage x gather ----
            for (int t = tid; t < cpad * 4; t += 256) {
                int e = t >> 2, r = t & 3;
                float4 v = make_float4(0.f, 0.f, 0.f, 0.f);
                if (e < c) {
                    int src = __ldg(idxn + base + e);
                    v = __ldg((const float4*)x + (size_t)src * 4 + r);
                }
                int q = e >> 1, hh = e & 1;
                float* c0 = (float*)&SM->Xq[q][2 * r];
                float* c1 = (float*)&SM->Xq[q][2 * r + 1];
                c0[hh]     = v.x;
                c0[2 + hh] = v.y;
                c1[hh]     = v.z;
                c1[2 + hh] = v.w;
            }
            // ---- precompute per-node segment descriptors (block-uniform) ----
            // BOTH aL and bL clamped into [0, c] so the packed fields are valid.
            if (tid < NB) {
                int ak = SM->sb[tid], bk = SM->sb[tid + 1];
                int aL = ak - base; if (aL < 0) aL = 0; if (aL > c) aL = c;
                int bL = bk - base; if (bL < 0) bL = 0; if (bL > c) bL = c;
                int flush = (bk > base && bk <= base + c && bk > ak) ? 1 : 0;
                SM->segd[tid] = aL | (bL << 9) | (flush << 31);
            }
            __syncthreads();

            // ---- h: 8-pair group per thread, bounded by qn ----
            H_COMPUTE(qn);
            __syncthreads();

            // ---- per-node masked rank-1 accumulation ----
            #pragma unroll 1
            for (int k = 0; k < NB; k++) {
                const int sd = SM->segd[k];
                const int aL = sd & 0x1FF;
                const int bL = (sd >> 9) & 0x1FF;
                if (bL > aL) {
                    const int qs = aL >> 1, qe = (bL - 1) >> 1;
                    const ull mlo = (aL & 1) ? 0xFFFFFFFF00000000ull : ~0ull;
                    const ull mhi = (bL & 1) ? 0x00000000FFFFFFFFull : ~0ull;
                    const ull* hp = &hrow[qs];
                    const ulonglong2* xp = xrow + (size_t)qs * XS;
                    if (qe == qs) {
                        ull h2 = *hp & (mlo & mhi);
                        ulonglong2 xv = *xp;
                        a0 = ffma2(h2, xv.x, a0); a1 = ffma2(h2, xv.y, a1);
                    } else {
                        {   // first (masked)
                            ull h2 = *hp & mlo;
                            ulonglong2 xv = *xp;
                            a0 = ffma2(h2, xv.x, a0); a1 = ffma2(h2, xv.y, a1);
                            hp++; xp += XS;
                        }
                        int q = qs + 1;
                        if ((q & 1) && q < qe) {       // align to even q
                            ull h2 = *hp;
                            ulonglong2 xv = *xp;
                            a0 = ffma2(h2, xv.x, a0); a1 = ffma2(h2, xv.y, a1);
                            hp++; xp += XS; q++;
                        }
                        #pragma unroll 2
                        for (; q + 1 < qe; q += 2) {   // two pairs: LDS.128 on h
                            ulonglong2 h4 = *(const ulonglong2*)hp;
                            ulonglong2 xv0 = xp[0];
                            ulonglong2 xv1 = xp[XS];
                            a0 = ffma2(h4.x, xv0.x, a0); a1 = ffma2(h4.x, xv0.y, a1);
                            a0 = ffma2(h4.y, xv1.x, a0); a1 = ffma2(h4.y, xv1.y, a1);
                            hp += 2; xp += 2 * XS;
                        }
                        if (q < qe) {
                            ull h2 = *hp;
                            ulonglong2 xv = *xp;
                            a0 = ffma2(h2, xv.x, a0); a1 = ffma2(h2, xv.y, a1);
                            hp++; xp += XS; q++;
                        }
                        {   // last (masked)
                            ull h2 = *hp & mhi;
                            ulonglong2 xv = *xp;
                            a0 = ffma2(h2, xv.x, a0); a1 = ffma2(h2, xv.y, a1);
                        }
                    }
                }
                if (sd < 0) {                          // flush flag (bit 31)
                    float2 fa = unpk(a0), fb = unpk(a1);
                    SM->Mbuf[k][tid] = pk2(fa.x + fa.y, fb.x + fb.y);
                    a0 = 0ull; a1 = 0ull;
                }
            }

            // ---- S phase: warp wS owns node wS (lanes 0-15, i = laneS) ----
            if (laneS < 16) {
                const int sd = SM->segd[wS];
                const int aL = sd & 0x1FF;
                const int bL = (sd >> 9) & 0x1FF;
                if (bL > aL) {
                    const int qs = aL >> 1, qe = (bL - 1) >> 1;
                    const ull mlo = (aL & 1) ? 0xFFFFFFFF00000000ull : ~0ull;
                    const ull mhi = (bL & 1) ? 0x00000000FFFFFFFFull : ~0ull;
                    const ull* xrp = (const ull*)&SM->Xq[qs][laneS >> 1] + (laneS & 1);
                    ull x2 = *xrp & mlo;
                    if (qe == qs) x2 &= mhi;
                    aS = add2(aS, x2);
                    xrp += 2 * XS;
                    for (int q = qs + 1; q < qe; q++, xrp += 2 * XS)
                        aS = add2(aS, *xrp);
                    if (qe > qs) aS = add2(aS, *xrp & mhi);
                }
                if (sd < 0) {
                    float2 fs = unpk(aS);
                    ((float*)SM->Sb2)[wS * 16 + laneS] = fs.x + fs.y;
                    aS = 0ull;
                }
            }
            __syncthreads();
        }

        // ---- GEMM: 8-way k-split, each warp covers all 8 nodes ----
        {
            const int w = tid >> 5, lane = tid & 31;
            const int o = lane & 15, gh = lane >> 4;     // gh: node half
            ull s0g = 0ull, s1g = 0ull, s2g = 0ull, s3g = 0ull;
            const ulonglong2* wp = &W2Q[w * 16][o];
            const ull* mb0 = &SM->Mbuf[gh * 4 + 0][2 * (w * 16)];
            const ull* mb1 = &SM->Mbuf[gh * 4 + 1][2 * (w * 16)];
            const ull* mb2 = &SM->Mbuf[gh * 4 + 2][2 * (w * 16)];
            const ull* mb3 = &SM->Mbuf[gh * 4 + 3][2 * (w * 16)];
            #pragma unroll 4
            for (int it = 0; it < 16; it++) {
                ulonglong2 w2 = __ldg(wp); wp += 16;
                ulonglong2 m0 = *(const ulonglong2*)mb0; mb0 += 2;
                ulonglong2 m1 = *(const ulonglong2*)mb1; mb1 += 2;
                ulonglong2 m2 = *(const ulonglong2*)mb2; mb2 += 2;
                ulonglong2 m3 = *(const ulonglong2*)mb3; mb3 += 2;
                s0g = ffma2(m0.x, w2.x, s0g); s0g = ffma2(m0.y, w2.y, s0g);
                s1g = ffma2(m1.x, w2.x, s1g); s1g = ffma2(m1.y, w2.y, s1g);
                s2g = ffma2(m2.x, w2.x, s2g); s2g = ffma2(m2.y, w2.y, s2g);
                s3g = ffma2(m3.x, w2.x, s3g); s3g = ffma2(m3.y, w2.y, s3g);
            }
            ull* Gred = &SM->Hp[0][0];       // Hp dead after last chunk
            Gred[w * 128 + (gh * 4 + 0) * 16 + o] = s0g;
            Gred[w * 128 + (gh * 4 + 1) * 16 + o] = s1g;
            Gred[w * 128 + (gh * 4 + 2) * 16 + o] = s2g;
            Gred[w * 128 + (gh * 4 + 3) * 16 + o] = s3g;
        }
        __syncthreads();
        if (tid < 128) {
            const int g = tid >> 4, o = tid & 15;
            const ull* Gred = &SM->Hp[0][0];
            ull s = Gred[g * 16 + o];
            #pragma unroll
            for (int w = 1; w < 8; w++) s = add2(s, Gred[w * 128 + g * 16 + o]);
            #pragma unroll
            for (int pp = 0; pp < 8; pp++)
                s = ffma2(SM->Sb2[g][pp], __ldg(&b2P[0][0] + pp * 16 + o), s);
            if (g < nn) {
                float2 f = unpk(s);
                float d = __ldg(degs + t0 + g);
                out[(t0 + g) * 16 + o] = (d > 0.f) ? (f.x + f.y) / d : 0.f;
            }
        }
    } else {
        // ================= node-0 slice blocks =================
        const int e0e = (int)__ldg(degs);   // node 0 owns edges [0, degs[0])
        ull a0 = 0ull, a1 = 0ull, aS = 0ull;
        __syncthreads();

        for (int base = bx * CH; base < e0e; base += EX * CH) {
            const int c = min(CH, e0e - base);
            const int cpad = (c + 1) & ~1;
            const int qn = cpad >> 1;

            for (int k = tid; k < cpad * EDGE_F; k += 256) {
                int e = k / EDGE_F, f = k - e * EDGE_F;
                EFf[f * (2 * EFS) + e] =
                    (e < c) ? __ldg(ef + (size_t)base * EDGE_F + k) : 0.f;
            }
            for (int t = tid; t < cpad * 4; t += 256) {
                int e = t >> 2, r = t & 3;
                float4 v = make_float4(0.f, 0.f, 0.f, 0.f);
                if (e < c) {
                    int src = __ldg(idxn + base + e);
                    v = __ldg((const float4*)x + (size_t)src * 4 + r);
                }
                int q = e >> 1, hh = e & 1;
                float* c0 = (float*)&SM->Xq[q][2 * r];
                float* c1 = (float*)&SM->Xq[q][2 * r + 1];
                c0[hh]     = v.x;
                c0[2 + hh] = v.y;
                c1[hh]     = v.z;
                c1[2 + hh] = v.w;
            }
            __syncthreads();

            H_COMPUTE(qn);
            __syncthreads();

            {
                const ull* hp = hrow;
                const ulonglong2* xp = xrow;
                int q = 0;
                #pragma unroll 2
                for (; q + 1 < qn; q += 2) {
                    ulonglong2 h4 = *(const ulonglong2*)hp;
                    ulonglong2 xv0 = xp[0];
                    ulonglong2 xv1 = xp[XS];
                    a0 = ffma2(h4.x, xv0.x, a0); a1 = ffma2(h4.x, xv0.y, a1);
                    a0 = ffma2(h4.y, xv1.x, a0); a1 = ffma2(h4.y, xv1.y, a1);
                    hp += 2; xp += 2 * XS;
                }
                if (q < qn) {
                    ull h2 = *hp;
                    ulonglong2 xv = *xp;
                    a0 = ffma2(h2, xv.x, a0); a1 = ffma2(h2, xv.y, a1);
                }
            }
            if (tid < 16) {
                const ull* xrp = (const ull*)&SM->Xq[0][tid >> 1] + (tid & 1);
                for (int q = 0; q < qn; q++, xrp += 2 * XS)
                    aS = add2(aS, *xrp);
            }
            __syncthreads();
        }
        {
            float2 fa = unpk(a0), fb = unpk(a1);
            Mg0x[bx][tid] = pk2(fa.x + fa.y, fb.x + fb.y);
            if (tid < 16) {
                float2 fs = unpk(aS);
                Sg0x[bx][tid] = fs.x + fs.y;
            }
        }

        // ---- last-arriving EX block reduces node 0 ----
        __threadfence();
        __syncthreads();
        if (tid == 0)
            SM->sb[0] = (atomicAdd(&Ctr0, 1) == EX - 1) ? 1 : 0;
        __syncthreads();
        if (SM->sb[0]) {
            __threadfence();
            float* wred = (float*)&SM->Mbuf[0][0];
            float* ssum = wred + 128;
            const int lane = tid & 31, w = tid >> 5;

            ull m = Mg0x[0][tid];
            #pragma unroll
            for (int e2 = 1; e2 < EX; e2++) m = add2(m, Mg0x[e2][tid]);
            if (tid < 16) {
                float s = 0.f;
                #pragma unroll
                for (int e2 = 0; e2 < EX; e2++) s += Sg0x[e2][tid];
                ssum[tid] = s;
            }
            float po[16];
            #pragma unroll
            for (int o = 0; o < 16; o++) {
                ull wk = ((const ull*)&W2Q[tid >> 1][o])[tid & 1];
                ull t2 = ffma2(m, wk, 0ull);
                float2 f = unpk(t2);
                po[o] = f.x + f.y;
            }
            #pragma unroll
            for (int o = 0; o < 16; o++)
                #pragma unroll
                for (int off = 16; off; off >>= 1)
                    po[o] += __shfl_down_sync(0xffffffffu, po[o], off);
            if (lane == 0)
                #pragma unroll
                for (int o = 0; o < 16; o++) wred[w * 16 + o] = po[o];
            __syncthreads();
            if (tid < 16) {
                float t = 0.f;
                #pragma unroll
                for (int w2 = 0; w2 < 8; w2++) t += wred[w2 * 16 + tid];
                float s2 = 0.f;
                #pragma unroll
                for (int pp = 0; pp < 8; pp++) {
                    ull q = ffma2(pk2(ssum[2 * pp], ssum[2 * pp + 1]),
                                  b2P[pp][tid], 0ull);
                    float2 f = unpk(q);
                    s2 += f.x + f.y;
                }
                float d = __ldg(degs);
                out[tid] = (d > 0.f) ? (t + s2) / d : 0.f;
            }
            if (tid == 0) Ctr0 = 0;
        }
    }
}

// ---------------------------------------------------------------------------
extern "C" void kernel_launch(void* const* d_in, const int* in_sizes, int n_in,
                              void* d_out, int out_size)
{
    const float* x    = (const float*)d_in[0];
    const float* ef   = (const float*)d_in[1];
    const float* W1   = (const float*)d_in[2];
    const float* b1   = (const float*)d_in[3];
    const float* W2   = (const float*)d_in[4];
    const float* b2   = (const float*)d_in[5];
    const int*   idxn = (const int*)d_in[6];
    const float* degs = (const float*)d_in[8];
    float* out = (float*)d_out;

    const int E = in_sizes[6];
    static int smem_set = 0;
    if (!smem_set) {
        cudaFuncSetAttribute(fused_kernel,
                             cudaFuncAttributeMaxDynamicSharedMemorySize,
                             (int)sizeof(SmemT));
        smem_set = 1;
    }

    scan1_kernel<<<SCAN_NB + 1, SCAN_B>>>(degs, W2, b2);
    fused_kernel<<<EX + NBLK, 256, sizeof(SmemT)>>>(x, ef, W1, b1, idxn, degs, out, E);
}